// round 5
// baseline (speedup 1.0000x reference)
#include <cuda_runtime.h>
#include <stdint.h>

#define BATCH 4
#define NSEQ  4096
#define DDIM  1024
#define EDIM  1024

// ---------------- scratch (device globals; no allocations allowed) -------------
__device__ int8_t g_xd1[(size_t)BATCH*NSEQ*DDIM], g_xd0[(size_t)BATCH*NSEQ*DDIM];
__device__ int8_t g_yd1[(size_t)BATCH*NSEQ*DDIM], g_yd0[(size_t)BATCH*NSEQ*DDIM];
__device__ int8_t g_wqd1[(size_t)EDIM*DDIM], g_wqd0[(size_t)EDIM*DDIM];
__device__ int8_t g_wkd1[(size_t)EDIM*DDIM], g_wkd0[(size_t)EDIM*DDIM];
__device__ int8_t g_wvd1[(size_t)EDIM*DDIM], g_wvd0[(size_t)EDIM*DDIM];
__device__ int8_t g_wod1[(size_t)DDIM*EDIM], g_wod0[(size_t)DDIM*EDIM];
__device__ float  g_q[(size_t)BATCH*NSEQ*EDIM], g_k[(size_t)BATCH*NSEQ*EDIM], g_v[(size_t)BATCH*NSEQ*EDIM];
__device__ int8_t g_qd1[(size_t)BATCH*NSEQ*EDIM], g_qd0[(size_t)BATCH*NSEQ*EDIM];
__device__ int8_t g_kd1[(size_t)BATCH*NSEQ*EDIM], g_kd0[(size_t)BATCH*NSEQ*EDIM];
__device__ float  g_S[(size_t)BATCH*NSEQ*NSEQ];
__device__ int8_t g_pd1[(size_t)BATCH*NSEQ*NSEQ], g_pd0[(size_t)BATCH*NSEQ*NSEQ];
__device__ float  g_vt[(size_t)BATCH*EDIM*NSEQ];
__device__ int8_t g_vtd1[(size_t)BATCH*EDIM*NSEQ], g_vtd0[(size_t)BATCH*EDIM*NSEQ];
__device__ float  g_ctx[(size_t)BATCH*NSEQ*EDIM];
__device__ int8_t g_cd1[(size_t)BATCH*NSEQ*EDIM], g_cd0[(size_t)BATCH*NSEQ*EDIM];
// scales
__device__ float g_sx[BATCH*NSEQ], g_sy[BATCH*NSEQ];
__device__ float g_swq[EDIM], g_swk[EDIM], g_swv[EDIM], g_swo[DDIM];
__device__ float g_sq[BATCH*NSEQ], g_sk[BATCH*NSEQ];
__device__ float g_sp[BATCH*NSEQ];
__device__ float g_svt[BATCH*EDIM];
__device__ float g_sc[BATCH*NSEQ];

// ---------------- helpers ----------------
__device__ __forceinline__ uint32_t smem_u32(const void* p) {
    uint32_t a;
    asm("{ .reg .u64 t; cvta.to.shared.u64 t, %1; cvt.u32.u64 %0, t; }" : "=r"(a) : "l"(p));
    return a;
}
__device__ __forceinline__ void cpa16(uint32_t dst, const void* src) {
    asm volatile("cp.async.cg.shared.global [%0], [%1], 16;" :: "r"(dst), "l"(src));
}

#define MMA_S8(c, a, b) \
    asm volatile("mma.sync.aligned.m16n8k32.row.col.s32.s8.s8.s32 " \
                 "{%0,%1,%2,%3},{%4,%5,%6,%7},{%8,%9},{%0,%1,%2,%3};\n" \
                 : "+r"(c[0]), "+r"(c[1]), "+r"(c[2]), "+r"(c[3]) \
                 : "r"(a[0]), "r"(a[1]), "r"(a[2]), "r"(a[3]), "r"(b[0]), "r"(b[1]))

// ---------------- per-row quantize: v = s*(128*d1 + d0), s = rowmax/16256 ------
template<int KLEN>
__global__ __launch_bounds__(256)
void quant_rows(const float* __restrict__ src, int8_t* __restrict__ d1,
                int8_t* __restrict__ d0, float* __restrict__ scale)
{
    __shared__ float red[8];
    const size_t base = (size_t)blockIdx.x * KLEN;
    const int tid = threadIdx.x;
    constexpr int NV = KLEN / 1024;      // float4s per thread

    float4 v[NV];
    float lmax = 0.0f;
#pragma unroll
    for (int i = 0; i < NV; i++) {
        v[i] = *(const float4*)(src + base + (i * 256 + tid) * 4);
        lmax = fmaxf(lmax, fmaxf(fmaxf(fabsf(v[i].x), fabsf(v[i].y)),
                                 fmaxf(fabsf(v[i].z), fabsf(v[i].w))));
    }
#pragma unroll
    for (int o = 16; o; o >>= 1) lmax = fmaxf(lmax, __shfl_xor_sync(0xffffffffu, lmax, o));
    if ((tid & 31) == 0) red[tid >> 5] = lmax;
    __syncthreads();
    float m = red[0];
#pragma unroll
    for (int j = 1; j < 8; j++) m = fmaxf(m, red[j]);
    m = fmaxf(m, 1e-20f);
    if (tid == 0) scale[blockIdx.x] = m * (1.0f / 16256.0f);
    const float inv = 16256.0f / m;

#pragma unroll
    for (int i = 0; i < NV; i++) {
        float vs[4] = {v[i].x, v[i].y, v[i].z, v[i].w};
        char c1[4], c0[4];
#pragma unroll
        for (int j = 0; j < 4; j++) {
            float t  = rintf(vs[j] * inv);
            float t1 = rintf(t * (1.0f / 128.0f));
            float t0 = t - 128.0f * t1;
            c1[j] = (char)(int)t1;
            c0[j] = (char)(int)t0;
        }
        size_t o = (base + (size_t)(i * 256 + tid) * 4);
        *(char4*)(d1 + o) = make_char4(c1[0], c1[1], c1[2], c1[3]);
        *(char4*)(d0 + o) = make_char4(c0[0], c0[1], c0[2], c0[3]);
    }
}

// ---------------- fp32 transpose per batch: [NSEQ, EDIM] -> [EDIM, NSEQ] -------
__global__ __launch_bounds__(256)
void transpose_f32(const float* __restrict__ in, float* __restrict__ out)
{
    __shared__ float t[64][72];
    const int z = blockIdx.z;
    in  += (size_t)z * NSEQ * EDIM;
    out += (size_t)z * EDIM * NSEQ;
    const int x0 = blockIdx.x * 64;   // E tile
    const int y0 = blockIdx.y * 64;   // seq tile
    const int tid = threadIdx.x;
    const int r = tid >> 3, c = (tid & 7) * 8;
#pragma unroll
    for (int i = 0; i < 2; i++) {
        float4 a = *(const float4*)(in + (size_t)(y0 + r + 32*i) * EDIM + x0 + c);
        float4 b = *(const float4*)(in + (size_t)(y0 + r + 32*i) * EDIM + x0 + c + 4);
        *(float4*)&t[r + 32*i][c]     = a;
        *(float4*)&t[r + 32*i][c + 4] = b;
    }
    __syncthreads();
#pragma unroll
    for (int i = 0; i < 2; i++) {
        int orow = r + 32*i;
        float tmp[8];
#pragma unroll
        for (int j = 0; j < 8; j++) tmp[j] = t[c + j][orow];
        *(float4*)(out + (size_t)(x0 + orow) * NSEQ + y0 + c)     = *(float4*)tmp;
        *(float4*)(out + (size_t)(x0 + orow) * NSEQ + y0 + c + 4) = *(float4*)(tmp + 4);
    }
}

// ---------------- int8 two-digit GEMM: C[M,N] = sA[m]*sB[n]*(A_digits @ B_digits^T)
// A: [M,K] row-major int8 digits. B: [N,K] row-major int8 digits.
// CTA tile 128x128, K_TILE=128 bytes, 3-stage cp.async. 8 warps, each 64x32.
// BIAS: 0 = none; 1 = add bias[n].

#define NSTAGE   3
#define ARR_B    (128 * 144)
#define STAGE_B  (4 * ARR_B)                 // A1,A0,B1,B0 = 73728
#define SMEM_B   (NSTAGE * STAGE_B)          // 221184

template<int BIAS>
__global__ __launch_bounds__(256, 1)
void gemm_s8(const int8_t* __restrict__ A1, const int8_t* __restrict__ A0,
             const int8_t* __restrict__ B1, const int8_t* __restrict__ B0,
             const float* __restrict__ sA, const float* __restrict__ sB,
             float* __restrict__ outF, const float* __restrict__ bias,
             int M, int N, int K, long long strA, long long strB, long long strC)
{
    extern __shared__ __align__(16) char dsm[];
    const uint32_t sb = smem_u32(dsm);

    const int z = blockIdx.z;
    A1 += (size_t)z * strA;  A0 += (size_t)z * strA;
    B1 += (size_t)z * strB;  B0 += (size_t)z * strB;
    sA += (size_t)z * M;     sB += (size_t)z * N;

    const int tid = threadIdx.x;
    const int lane = tid & 31;
    const int warp = tid >> 5;
    const int m0 = blockIdx.y * 128;
    const int n0 = blockIdx.x * 128;

    const int wm0 = (warp & 1) * 64;          // 2 warps along M
    const int wn0 = (warp >> 1) * 32;         // 4 warps along N
    const int arow = lane & 15;
    const int acolb = (lane >> 4) * 16;       // byte offset within 32B k-step
    const int brow = lane & 7;
    const int bcolb = ((lane >> 3) & 1) * 16;

    const int nk = K >> 7;                    // K-tiles of 128

    const int lr = tid >> 3;                  // 0..31
    const int lcb = (tid & 7) * 16;           // byte chunk

    auto load_stage = [&](int kt, int stg) {
        const uint32_t base = sb + stg * STAGE_B;
        const int kk = kt << 7;
#pragma unroll
        for (int j = 0; j < 4; j++) {
            const int row = lr + 32 * j;
            const uint32_t d = base + row * 144 + lcb;
            const size_t ga = (size_t)(m0 + row) * K + kk + lcb;
            const size_t gb = (size_t)(n0 + row) * K + kk + lcb;
            cpa16(d,             A1 + ga);
            cpa16(d + ARR_B,     A0 + ga);
            cpa16(d + 2*ARR_B,   B1 + gb);
            cpa16(d + 3*ARR_B,   B0 + gb);
        }
        asm volatile("cp.async.commit_group;" ::: "memory");
    };

    int hi[4][4][4], lo[4][4][4];
#pragma unroll
    for (int t = 0; t < 4; t++)
#pragma unroll
        for (int u = 0; u < 4; u++)
#pragma unroll
            for (int e = 0; e < 4; e++) { hi[t][u][e] = 0; lo[t][u][e] = 0; }

    load_stage(0, 0);
    if (nk > 1) load_stage(1, 1);

    for (int kt = 0; kt < nk; kt++) {
        if (kt + 1 < nk) asm volatile("cp.async.wait_group 1;" ::: "memory");
        else             asm volatile("cp.async.wait_group 0;" ::: "memory");
        __syncthreads();

        if (kt + 2 < nk) load_stage(kt + 2, (kt + 2) % NSTAGE);

        const uint32_t base = sb + (kt % NSTAGE) * STAGE_B;

#pragma unroll
        for (int ks = 0; ks < 4; ks++) {
            const int kb = ks * 32;
            uint32_t a1[4][4], a0[4][4], b1[4][2], b0[4][2];
#pragma unroll
            for (int t = 0; t < 4; t++) {
                uint32_t ad = base + (uint32_t)(wm0 + t*16 + arow) * 144 + kb + acolb;
                asm volatile("ldmatrix.sync.aligned.m8n8.x4.shared.b16 {%0,%1,%2,%3}, [%4];\n"
                             : "=r"(a1[t][0]), "=r"(a1[t][1]), "=r"(a1[t][2]), "=r"(a1[t][3]) : "r"(ad));
                asm volatile("ldmatrix.sync.aligned.m8n8.x4.shared.b16 {%0,%1,%2,%3}, [%4];\n"
                             : "=r"(a0[t][0]), "=r"(a0[t][1]), "=r"(a0[t][2]), "=r"(a0[t][3]) : "r"(ad + ARR_B));
            }
#pragma unroll
            for (int u = 0; u < 4; u++) {
                uint32_t bd = base + 2*ARR_B + (uint32_t)(wn0 + u*8 + brow) * 144 + kb + bcolb;
                asm volatile("ldmatrix.sync.aligned.m8n8.x2.shared.b16 {%0,%1}, [%2];\n"
                             : "=r"(b1[u][0]), "=r"(b1[u][1]) : "r"(bd));
                asm volatile("ldmatrix.sync.aligned.m8n8.x2.shared.b16 {%0,%1}, [%2];\n"
                             : "=r"(b0[u][0]), "=r"(b0[u][1]) : "r"(bd + ARR_B));
            }
#pragma unroll
            for (int t = 0; t < 4; t++)
#pragma unroll
                for (int u = 0; u < 4; u++) MMA_S8(hi[t][u], a1[t], b1[u]);
#pragma unroll
            for (int t = 0; t < 4; t++)
#pragma unroll
                for (int u = 0; u < 4; u++) MMA_S8(lo[t][u], a1[t], b0[u]);
#pragma unroll
            for (int t = 0; t < 4; t++)
#pragma unroll
                for (int u = 0; u < 4; u++) MMA_S8(lo[t][u], a0[t], b1[u]);
        }
    }

    // ---- epilogue: C = sA*sB*(16384*hi + 128*lo) (+ bias) ----
    const size_t cbase = (size_t)z * strC;
#pragma unroll
    for (int t = 0; t < 4; t++) {
        const int gm = m0 + wm0 + t * 16 + (lane >> 2);
        const float sa0 = sA[gm], sa1 = sA[gm + 8];
#pragma unroll
        for (int u = 0; u < 4; u++) {
            const int gn = n0 + wn0 + u * 8 + (lane & 3) * 2;
            const float sb0 = sB[gn], sb1 = sB[gn + 1];
            float v00 = sa0 * sb0 * (16384.0f * (float)hi[t][u][0] + 128.0f * (float)lo[t][u][0]);
            float v01 = sa0 * sb1 * (16384.0f * (float)hi[t][u][1] + 128.0f * (float)lo[t][u][1]);
            float v10 = sa1 * sb0 * (16384.0f * (float)hi[t][u][2] + 128.0f * (float)lo[t][u][2]);
            float v11 = sa1 * sb1 * (16384.0f * (float)hi[t][u][3] + 128.0f * (float)lo[t][u][3]);
            if (BIAS) {
                v00 += bias[gn]; v01 += bias[gn + 1];
                v10 += bias[gn]; v11 += bias[gn + 1];
            }
            *(float2*)(outF + cbase + (size_t)gm * N + gn) = make_float2(v00, v01);
            *(float2*)(outF + cbase + (size_t)(gm + 8) * N + gn) = make_float2(v10, v11);
        }
    }
}

// ---------------- row softmax (scaled) emitting int8 digit pairs ---------------
__global__ __launch_bounds__(256)
void softmax_s8(const float* __restrict__ S, int8_t* __restrict__ Pd1,
                int8_t* __restrict__ Pd0, float* __restrict__ sp, float scale)
{
    __shared__ float buf[NSEQ];
    __shared__ float red[8];
    const size_t base = (size_t)blockIdx.x * NSEQ;
    const int tid = threadIdx.x;

    float lmax = -1e30f;
#pragma unroll
    for (int i = 0; i < NSEQ / (256 * 4); i++) {
        int idx = (i * 256 + tid) * 4;
        float4 v = *(const float4*)(S + base + idx);
        buf[idx] = v.x; buf[idx + 1] = v.y; buf[idx + 2] = v.z; buf[idx + 3] = v.w;
        lmax = fmaxf(lmax, fmaxf(fmaxf(v.x, v.y), fmaxf(v.z, v.w)));
    }
#pragma unroll
    for (int o = 16; o; o >>= 1) lmax = fmaxf(lmax, __shfl_xor_sync(0xffffffffu, lmax, o));
    if ((tid & 31) == 0) red[tid >> 5] = lmax;
    __syncthreads();
    float rmax = red[0];
#pragma unroll
    for (int j = 1; j < 8; j++) rmax = fmaxf(rmax, red[j]);
    __syncthreads();

    float lsum = 0.0f;
#pragma unroll
    for (int i = 0; i < NSEQ / (256 * 4); i++) {
        int idx = (i * 256 + tid) * 4;
#pragma unroll
        for (int j = 0; j < 4; j++) {
            float e = expf(scale * (buf[idx + j] - rmax));
            buf[idx + j] = e;
            lsum += e;
        }
    }
#pragma unroll
    for (int o = 16; o; o >>= 1) lsum += __shfl_xor_sync(0xffffffffu, lsum, o);
    if ((tid & 31) == 0) red[tid >> 5] = lsum;
    __syncthreads();
    float rsum = red[0];
#pragma unroll
    for (int j = 1; j < 8; j++) rsum += red[j];
    const float rinv = 1.0f / rsum;
    if (tid == 0) sp[blockIdx.x] = rinv * (1.0f / 16256.0f);

#pragma unroll
    for (int i = 0; i < NSEQ / (256 * 4); i++) {
        int idx = (i * 256 + tid) * 4;
        char c1[4], c0[4];
#pragma unroll
        for (int j = 0; j < 4; j++) {
            float t  = rintf(buf[idx + j] * 16256.0f);   // e in (0,1]
            float t1 = rintf(t * (1.0f / 128.0f));
            float t0 = t - 128.0f * t1;
            c1[j] = (char)(int)t1;
            c0[j] = (char)(int)t0;
        }
        *(char4*)(Pd1 + base + idx) = make_char4(c1[0], c1[1], c1[2], c1[3]);
        *(char4*)(Pd0 + base + idx) = make_char4(c0[0], c0[1], c0[2], c0[3]);
    }
}

// ---------------- host ----------------
extern "C" void kernel_launch(void* const* d_in, const int* in_sizes, int n_in,
                              void* d_out, int out_size)
{
    const float* x  = (const float*)d_in[0];
    const float* y  = (const float*)d_in[1];
    const float* Wq = (const float*)d_in[2];
    const float* Wk = (const float*)d_in[3];
    const float* Wv = (const float*)d_in[4];
    const float* Wo = (const float*)d_in[5];
    const float* bo = (const float*)d_in[6];
    float* out = (float*)d_out;

#define GET(sym, var) void* var; cudaGetSymbolAddress(&var, sym)
    GET(g_xd1, xd1); GET(g_xd0, xd0); GET(g_yd1, yd1); GET(g_yd0, yd0);
    GET(g_wqd1, wqd1); GET(g_wqd0, wqd0); GET(g_wkd1, wkd1); GET(g_wkd0, wkd0);
    GET(g_wvd1, wvd1); GET(g_wvd0, wvd0); GET(g_wod1, wod1); GET(g_wod0, wod0);
    GET(g_q, qf); GET(g_k, kf); GET(g_v, vf);
    GET(g_qd1, qd1); GET(g_qd0, qd0); GET(g_kd1, kd1); GET(g_kd0, kd0);
    GET(g_S, sS); GET(g_pd1, pd1); GET(g_pd0, pd0);
    GET(g_vt, vt); GET(g_vtd1, vtd1); GET(g_vtd0, vtd0);
    GET(g_ctx, ctx); GET(g_cd1, cd1); GET(g_cd0, cd0);
    GET(g_sx, sx); GET(g_sy, sy);
    GET(g_swq, swq); GET(g_swk, swk); GET(g_swv, swv); GET(g_swo, swo);
    GET(g_sq, sq); GET(g_sk, sk); GET(g_sp, sp); GET(g_svt, svt); GET(g_sc, sc);
#undef GET

    cudaFuncSetAttribute(gemm_s8<0>, cudaFuncAttributeMaxDynamicSharedMemorySize, SMEM_B);
    cudaFuncSetAttribute(gemm_s8<1>, cudaFuncAttributeMaxDynamicSharedMemorySize, SMEM_B);

    const int MBN = BATCH * NSEQ;            // 16384

    // 1) quantize inputs + weights (per-row, K contiguous)
    quant_rows<1024><<<MBN, 256>>>(x, (int8_t*)xd1, (int8_t*)xd0, (float*)sx);
    quant_rows<1024><<<MBN, 256>>>(y, (int8_t*)yd1, (int8_t*)yd0, (float*)sy);
    quant_rows<1024><<<EDIM, 256>>>(Wq, (int8_t*)wqd1, (int8_t*)wqd0, (float*)swq);
    quant_rows<1024><<<EDIM, 256>>>(Wk, (int8_t*)wkd1, (int8_t*)wkd0, (float*)swk);
    quant_rows<1024><<<EDIM, 256>>>(Wv, (int8_t*)wvd1, (int8_t*)wvd0, (float*)swv);
    quant_rows<1024><<<DDIM, 256>>>(Wo, (int8_t*)wod1, (int8_t*)wod0, (float*)swo);

    // 2) projections: q = y @ Wq^T, k = x @ Wk^T, v = x @ Wv^T  (fp32 out)
    {
        dim3 grid(EDIM / 128, MBN / 128, 1);
        gemm_s8<0><<<grid, 256, SMEM_B>>>((int8_t*)yd1, (int8_t*)yd0, (int8_t*)wqd1, (int8_t*)wqd0,
                                          (float*)sy, (float*)swq, (float*)qf, nullptr,
                                          MBN, EDIM, DDIM, 0, 0, 0);
        gemm_s8<0><<<grid, 256, SMEM_B>>>((int8_t*)xd1, (int8_t*)xd0, (int8_t*)wkd1, (int8_t*)wkd0,
                                          (float*)sx, (float*)swk, (float*)kf, nullptr,
                                          MBN, EDIM, DDIM, 0, 0, 0);
        gemm_s8<0><<<grid, 256, SMEM_B>>>((int8_t*)xd1, (int8_t*)xd0, (int8_t*)wvd1, (int8_t*)wvd0,
                                          (float*)sx, (float*)swv, (float*)vf, nullptr,
                                          MBN, EDIM, DDIM, 0, 0, 0);
    }

    // 3) quantize q, k per row
    quant_rows<1024><<<MBN, 256>>>((float*)qf, (int8_t*)qd1, (int8_t*)qd0, (float*)sq);
    quant_rows<1024><<<MBN, 256>>>((float*)kf, (int8_t*)kd1, (int8_t*)kd0, (float*)sk);

    // 4) scores: S[b] = q[b] @ k[b]^T   (M=N=4096, K=1024, fp32 out)
    {
        dim3 grid(NSEQ / 128, NSEQ / 128, BATCH);
        gemm_s8<0><<<grid, 256, SMEM_B>>>((int8_t*)qd1, (int8_t*)qd0, (int8_t*)kd1, (int8_t*)kd0,
                                          (float*)sq, (float*)sk, (float*)sS, nullptr,
                                          NSEQ, NSEQ, EDIM,
                                          (long long)NSEQ * EDIM, (long long)NSEQ * EDIM,
                                          (long long)NSEQ * NSEQ);
    }

    // 5) softmax (scale = 1/32) -> P digit pairs + per-row scale
    softmax_s8<<<BATCH * NSEQ, 256>>>((const float*)sS, (int8_t*)pd1, (int8_t*)pd0,
                                      (float*)sp, 1.0f / 32.0f);

    // 6) transpose V -> V^T fp32, quantize per E-row (K=4096)
    {
        dim3 grid(EDIM / 64, NSEQ / 64, BATCH);
        transpose_f32<<<grid, 256>>>((const float*)vf, (float*)vt);
    }
    quant_rows<4096><<<BATCH * EDIM, 256>>>((float*)vt, (int8_t*)vtd1, (int8_t*)vtd0, (float*)svt);

    // 7) ctx: C[b] = P[b] @ (V^T[b])^T  (M=4096, N=1024, K=4096, fp32 out)
    {
        dim3 grid(EDIM / 128, NSEQ / 128, BATCH);
        gemm_s8<0><<<grid, 256, SMEM_B>>>((int8_t*)pd1, (int8_t*)pd0, (int8_t*)vtd1, (int8_t*)vtd0,
                                          (float*)sp, (float*)svt, (float*)ctx, nullptr,
                                          NSEQ, EDIM, NSEQ,
                                          (long long)NSEQ * NSEQ, (long long)EDIM * NSEQ,
                                          (long long)NSEQ * EDIM);
    }

    // 8) quantize ctx, then out = ctx @ Wo^T + bo
    quant_rows<1024><<<MBN, 256>>>((float*)ctx, (int8_t*)cd1, (int8_t*)cd0, (float*)sc);
    {
        dim3 grid(DDIM / 128, MBN / 128, 1);
        gemm_s8<1><<<grid, 256, SMEM_B>>>((int8_t*)cd1, (int8_t*)cd0, (int8_t*)wod1, (int8_t*)wod0,
                                          (float*)sc, (float*)swo, out, bo,
                                          MBN, DDIM, EDIM, 0, 0, 0);
    }

    (void)in_sizes; (void)n_in; (void)out_size;
}

// round 6
// speedup vs baseline: 2.3182x; 2.3182x over previous
#include <cuda_runtime.h>
#include <cuda_bf16.h>
#include <stdint.h>

#define BATCH 4
#define NSEQ  4096
#define DDIM  1024
#define EDIM  1024

typedef __nv_bfloat16 bf16;

// ---------------- scratch (device globals; no allocations allowed) -------------
__device__ bf16 g_xh[(size_t)BATCH*NSEQ*DDIM], g_xl[(size_t)BATCH*NSEQ*DDIM];
__device__ bf16 g_yh[(size_t)BATCH*NSEQ*DDIM], g_yl[(size_t)BATCH*NSEQ*DDIM];
__device__ bf16 g_wqh[(size_t)EDIM*DDIM], g_wql[(size_t)EDIM*DDIM];
__device__ bf16 g_wkh[(size_t)EDIM*DDIM], g_wkl[(size_t)EDIM*DDIM];
__device__ bf16 g_wvh[(size_t)EDIM*DDIM], g_wvl[(size_t)EDIM*DDIM];
__device__ bf16 g_woh[(size_t)DDIM*EDIM], g_wol[(size_t)DDIM*EDIM];
__device__ bf16 g_qh[(size_t)BATCH*NSEQ*EDIM], g_ql[(size_t)BATCH*NSEQ*EDIM];
__device__ bf16 g_kh[(size_t)BATCH*NSEQ*EDIM], g_kl[(size_t)BATCH*NSEQ*EDIM];
__device__ bf16 g_vh[(size_t)BATCH*NSEQ*EDIM], g_vl[(size_t)BATCH*NSEQ*EDIM];
__device__ bf16 g_vth[(size_t)BATCH*EDIM*NSEQ], g_vtl[(size_t)BATCH*EDIM*NSEQ];
__device__ bf16 g_ph[(size_t)BATCH*NSEQ*NSEQ], g_pl[(size_t)BATCH*NSEQ*NSEQ];
__device__ bf16 g_ch[(size_t)BATCH*NSEQ*EDIM], g_cl[(size_t)BATCH*NSEQ*EDIM];
__device__ float g_spart[(size_t)BATCH*NSEQ*16];
__device__ float g_rinv[(size_t)BATCH*NSEQ];

// ---------------- helpers ----------------
__device__ __forceinline__ uint32_t smem_u32(const void* p) {
    uint32_t a;
    asm("{ .reg .u64 t; cvta.to.shared.u64 t, %1; cvt.u32.u64 %0, t; }" : "=r"(a) : "l"(p));
    return a;
}
__device__ __forceinline__ void cpa16(uint32_t dst, const void* src) {
    asm volatile("cp.async.cg.shared.global [%0], [%1], 16;" :: "r"(dst), "l"(src));
}

#define MMA_BF16(c, a, b) \
    asm volatile("mma.sync.aligned.m16n8k16.row.col.f32.bf16.bf16.f32 " \
                 "{%0,%1,%2,%3},{%4,%5,%6,%7},{%8,%9},{%0,%1,%2,%3};\n" \
                 : "+f"(c[0]), "+f"(c[1]), "+f"(c[2]), "+f"(c[3]) \
                 : "r"(a[0]), "r"(a[1]), "r"(a[2]), "r"(a[3]), "r"(b[0]), "r"(b[1]))

// ---------------- fp32 -> bf16 hi/lo split ----------------
__global__ void split_kernel(const float4* __restrict__ src,
                             bf16* __restrict__ hi, bf16* __restrict__ lo, int n4)
{
    int i = blockIdx.x * blockDim.x + threadIdx.x;
    if (i >= n4) return;
    float4 v = src[i];
    float vs[4] = {v.x, v.y, v.z, v.w};
    bf16 h[4], l[4];
#pragma unroll
    for (int j = 0; j < 4; j++) {
        h[j] = __float2bfloat16(vs[j]);
        l[j] = __float2bfloat16(vs[j] - __bfloat162float(h[j]));
    }
    __nv_bfloat162 h01; h01.x = h[0]; h01.y = h[1];
    __nv_bfloat162 h23; h23.x = h[2]; h23.y = h[3];
    __nv_bfloat162 l01; l01.x = l[0]; l01.y = l[1];
    __nv_bfloat162 l23; l23.x = l[2]; l23.y = l[3];
    reinterpret_cast<__nv_bfloat162*>(hi)[2*i]   = h01;
    reinterpret_cast<__nv_bfloat162*>(hi)[2*i+1] = h23;
    reinterpret_cast<__nv_bfloat162*>(lo)[2*i]   = l01;
    reinterpret_cast<__nv_bfloat162*>(lo)[2*i+1] = l23;
}

// ---------------- bf16 transpose per batch: in [NSEQ, EDIM] -> out [EDIM, NSEQ] ---
__global__ __launch_bounds__(256)
void transpose_k(const bf16* __restrict__ in, bf16* __restrict__ out)
{
    __shared__ bf16 t[64][72];
    const int z = blockIdx.z;
    in  += (size_t)z * NSEQ * EDIM;
    out += (size_t)z * EDIM * NSEQ;
    const int x0 = blockIdx.x * 64;
    const int y0 = blockIdx.y * 64;
    const int tid = threadIdx.x;
    const int r = tid >> 3, c = (tid & 7) * 8;
#pragma unroll
    for (int i = 0; i < 2; i++) {
        uint4 v = *(const uint4*)(in + (size_t)(y0 + r + 32*i) * EDIM + x0 + c);
        *(uint4*)&t[r + 32*i][c] = v;
    }
    __syncthreads();
#pragma unroll
    for (int i = 0; i < 2; i++) {
        int orow = r + 32*i;
        bf16 tmp[8];
#pragma unroll
        for (int j = 0; j < 8; j++) tmp[j] = t[c + j][orow];
        *(uint4*)(out + (size_t)(x0 + orow) * NSEQ + y0 + c) = *(uint4*)tmp;
    }
}

// ---------------- rowsum partials -> 1/sum ----------------
__global__ void rowsum_inv(const float* __restrict__ spart, float* __restrict__ rinv, int nrows)
{
    int r = blockIdx.x * 256 + threadIdx.x;
    if (r >= nrows) return;
    float s = 0.0f;
#pragma unroll
    for (int j = 0; j < 16; j++) s += spart[(size_t)r * 16 + j];
    rinv[r] = 1.0f / s;
}

// ---------------- HMMA split-bf16 GEMM: C[M,N] = (Ah+Al) @ (Bh+Bl)^T ----------
// CTA tile 128 (M) x 256 (N), K_TILE=32, 3-stage cp.async pipeline, 8 warps 64x64.
// OUT_MODE: 0 fp32; 1 split hi/lo bf16; 2 fp32+bias;
//           3 scores: E=exp(acc/32) split out + per-row partial sums;
//           4 PV: acc*rinv[row] split out.

#define NSTAGE   3
#define MAT_A    (128 * 80)
#define MAT_BB   (256 * 80)
#define OFF_AL   (MAT_A)
#define OFF_BH   (2 * MAT_A)
#define OFF_BL   (2 * MAT_A + MAT_BB)
#define STAGE_B  (2 * MAT_A + 2 * MAT_BB)
#define SMEM_B   (NSTAGE * STAGE_B)

template<int OUT_MODE>
__global__ __launch_bounds__(256, 1)
void gemm_hmma(const bf16* __restrict__ Ah, const bf16* __restrict__ Al,
               const bf16* __restrict__ Bh, const bf16* __restrict__ Bl,
               float* __restrict__ outF, bf16* __restrict__ outHi, bf16* __restrict__ outLo,
               const float* __restrict__ bias,
               float* __restrict__ spart, const float* __restrict__ rowscale,
               int M, int N, int K, long long sA, long long sB, long long sC)
{
    extern __shared__ __align__(16) char dsm[];
    __shared__ float part[128][4];
    const uint32_t sb = smem_u32(dsm);

    const int z = blockIdx.z;
    Ah += (size_t)z * sA;  Al += (size_t)z * sA;
    Bh += (size_t)z * sB;  Bl += (size_t)z * sB;

    const int tid = threadIdx.x;
    const int lane = tid & 31;
    const int warp = tid >> 5;
    const int m0 = blockIdx.y * 128;
    const int n0 = blockIdx.x * 256;

    const int wm0 = (warp & 1) * 64;
    const int wn0 = (warp >> 1) * 64;
    const int arow = lane & 15;
    const int acol = (lane >> 4) * 8;
    const int brow = lane & 7;
    const int bcol = ((lane >> 3) & 1) * 8;

    const int nk = K >> 5;

    const int ar0 = tid >> 2,          ac0 = (tid & 3);
    const int ar1 = (tid + 256) >> 2,  ac1 = ((tid + 256) & 3);

    auto load_stage = [&](int kt, int stg) {
        const uint32_t base = sb + stg * STAGE_B;
        const int kk = kt << 5;
        {
            uint32_t d = base + ar0 * 80 + ac0 * 16;
            const size_t g = (size_t)(m0 + ar0) * K + kk + ac0 * 8;
            cpa16(d,          Ah + g);
            cpa16(d + OFF_AL, Al + g);
        }
        {
            uint32_t d = base + ar1 * 80 + ac1 * 16;
            const size_t g = (size_t)(m0 + ar1) * K + kk + ac1 * 8;
            cpa16(d,          Ah + g);
            cpa16(d + OFF_AL, Al + g);
        }
#pragma unroll
        for (int i = 0; i < 4; i++) {
            const int idx = tid + 256 * i;
            const int br = idx >> 2, bc = idx & 3;
            uint32_t d = base + OFF_BH + br * 80 + bc * 16;
            const size_t g = (size_t)(n0 + br) * K + kk + bc * 8;
            cpa16(d,                   Bh + g);
            cpa16(d + (OFF_BL-OFF_BH), Bl + g);
        }
        asm volatile("cp.async.commit_group;" ::: "memory");
    };

    float acc[4][8][4];
#pragma unroll
    for (int t = 0; t < 4; t++)
#pragma unroll
        for (int u = 0; u < 8; u++)
#pragma unroll
            for (int e = 0; e < 4; e++) acc[t][u][e] = 0.0f;

    load_stage(0, 0);
    load_stage(1, 1);

    for (int kt = 0; kt < nk; kt++) {
        asm volatile("cp.async.wait_group 1;" ::: "memory");
        __syncthreads();

        if (kt + 2 < nk) load_stage(kt + 2, (kt + 2) % NSTAGE);
        else             asm volatile("cp.async.commit_group;" ::: "memory");

        const uint32_t base = sb + (kt % NSTAGE) * STAGE_B;

#pragma unroll
        for (int ks = 0; ks < 2; ks++) {
            const int kbyte = ks * 32;
            uint32_t ah[4][4], al[4][4], bh[8][2], bl[8][2];
#pragma unroll
            for (int t = 0; t < 4; t++) {
                uint32_t ad = base + (uint32_t)(wm0 + t*16 + arow) * 80 + kbyte + acol * 2;
                asm volatile("ldmatrix.sync.aligned.m8n8.x4.shared.b16 {%0,%1,%2,%3}, [%4];\n"
                             : "=r"(ah[t][0]), "=r"(ah[t][1]), "=r"(ah[t][2]), "=r"(ah[t][3]) : "r"(ad));
                asm volatile("ldmatrix.sync.aligned.m8n8.x4.shared.b16 {%0,%1,%2,%3}, [%4];\n"
                             : "=r"(al[t][0]), "=r"(al[t][1]), "=r"(al[t][2]), "=r"(al[t][3]) : "r"(ad + OFF_AL));
            }
#pragma unroll
            for (int u = 0; u < 8; u++) {
                uint32_t bd = base + OFF_BH + (uint32_t)(wn0 + u*8 + brow) * 80 + kbyte + bcol * 2;
                asm volatile("ldmatrix.sync.aligned.m8n8.x2.shared.b16 {%0,%1}, [%2];\n"
                             : "=r"(bh[u][0]), "=r"(bh[u][1]) : "r"(bd));
                asm volatile("ldmatrix.sync.aligned.m8n8.x2.shared.b16 {%0,%1}, [%2];\n"
                             : "=r"(bl[u][0]), "=r"(bl[u][1]) : "r"(bd + (OFF_BL-OFF_BH)));
            }
#pragma unroll
            for (int t = 0; t < 4; t++)
#pragma unroll
                for (int u = 0; u < 8; u++) MMA_BF16(acc[t][u], ah[t], bh[u]);
#pragma unroll
            for (int t = 0; t < 4; t++)
#pragma unroll
                for (int u = 0; u < 8; u++) MMA_BF16(acc[t][u], ah[t], bl[u]);
#pragma unroll
            for (int t = 0; t < 4; t++)
#pragma unroll
                for (int u = 0; u < 8; u++) MMA_BF16(acc[t][u], al[t], bh[u]);
        }
    }

    // ---- epilogue ----
    const size_t cbase = (size_t)z * sC;
#pragma unroll
    for (int t = 0; t < 4; t++) {
        const int gm = m0 + wm0 + t * 16 + (lane >> 2);
        float rs0 = 0.0f, rs1 = 0.0f;
        float rv0 = 1.0f, rv1 = 1.0f;
        if (OUT_MODE == 4) {
            rv0 = rowscale[(size_t)z * M + gm];
            rv1 = rowscale[(size_t)z * M + gm + 8];
        }
#pragma unroll
        for (int u = 0; u < 8; u++) {
            const int gn = n0 + wn0 + u * 8 + (lane & 3) * 2;
            float v00 = acc[t][u][0], v01 = acc[t][u][1];
            float v10 = acc[t][u][2], v11 = acc[t][u][3];
            if (OUT_MODE == 2) {
                float b0 = bias[gn], b1 = bias[gn + 1];
                v00 += b0; v01 += b1; v10 += b0; v11 += b1;
            }
            if (OUT_MODE == 3) {
                v00 = __expf(v00 * 0.03125f);
                v01 = __expf(v01 * 0.03125f);
                v10 = __expf(v10 * 0.03125f);
                v11 = __expf(v11 * 0.03125f);
                rs0 += v00 + v01;
                rs1 += v10 + v11;
            }
            if (OUT_MODE == 4) {
                v00 *= rv0; v01 *= rv0; v10 *= rv1; v11 *= rv1;
            }
            if (OUT_MODE == 0 || OUT_MODE == 2) {
                *(float2*)(outF + cbase + (size_t)gm * N + gn) = make_float2(v00, v01);
                *(float2*)(outF + cbase + (size_t)(gm + 8) * N + gn) = make_float2(v10, v11);
            } else {
                bf16 h00 = __float2bfloat16(v00), h01 = __float2bfloat16(v01);
                bf16 h10 = __float2bfloat16(v10), h11 = __float2bfloat16(v11);
                __nv_bfloat162 hp0; hp0.x = h00; hp0.y = h01;
                __nv_bfloat162 hp1; hp1.x = h10; hp1.y = h11;
                __nv_bfloat162 lp0; lp0.x = __float2bfloat16(v00 - __bfloat162float(h00));
                                    lp0.y = __float2bfloat16(v01 - __bfloat162float(h01));
                __nv_bfloat162 lp1; lp1.x = __float2bfloat16(v10 - __bfloat162float(h10));
                                    lp1.y = __float2bfloat16(v11 - __bfloat162float(h11));
                *(__nv_bfloat162*)(outHi + cbase + (size_t)gm * N + gn) = hp0;
                *(__nv_bfloat162*)(outHi + cbase + (size_t)(gm + 8) * N + gn) = hp1;
                *(__nv_bfloat162*)(outLo + cbase + (size_t)gm * N + gn) = lp0;
                *(__nv_bfloat162*)(outLo + cbase + (size_t)(gm + 8) * N + gn) = lp1;
            }
        }
        if (OUT_MODE == 3) {
            rs0 += __shfl_xor_sync(0xffffffffu, rs0, 1);
            rs0 += __shfl_xor_sync(0xffffffffu, rs0, 2);
            rs1 += __shfl_xor_sync(0xffffffffu, rs1, 1);
            rs1 += __shfl_xor_sync(0xffffffffu, rs1, 2);
            if ((lane & 3) == 0) {
                part[wm0 + t * 16 + (lane >> 2)][warp >> 1] = rs0;
                part[wm0 + t * 16 + (lane >> 2) + 8][warp >> 1] = rs1;
            }
        }
    }
    if (OUT_MODE == 3) {
        __syncthreads();
        if (tid < 128) {
            float s = part[tid][0] + part[tid][1] + part[tid][2] + part[tid][3];
            spart[((size_t)z * M + m0 + tid) * 16 + blockIdx.x] = s;
        }
    }
}

// ---------------- host ----------------
extern "C" void kernel_launch(void* const* d_in, const int* in_sizes, int n_in,
                              void* d_out, int out_size)
{
    const float* x  = (const float*)d_in[0];
    const float* y  = (const float*)d_in[1];
    const float* Wq = (const float*)d_in[2];
    const float* Wk = (const float*)d_in[3];
    const float* Wv = (const float*)d_in[4];
    const float* Wo = (const float*)d_in[5];
    const float* bo = (const float*)d_in[6];
    float* out = (float*)d_out;

#define GET(sym, var) void* var; cudaGetSymbolAddress(&var, sym)
    GET(g_xh, xh); GET(g_xl, xl); GET(g_yh, yh); GET(g_yl, yl);
    GET(g_wqh, wqh); GET(g_wql, wql); GET(g_wkh, wkh); GET(g_wkl, wkl);
    GET(g_wvh, wvh); GET(g_wvl, wvl); GET(g_woh, woh); GET(g_wol, wol);
    GET(g_qh, qh); GET(g_ql, ql); GET(g_kh, kh); GET(g_kl, kl);
    GET(g_vh, vh); GET(g_vl, vl); GET(g_vth, vth); GET(g_vtl, vtl);
    GET(g_ph, ph); GET(g_pl, pl); GET(g_ch, ch); GET(g_cl, cl);
    GET(g_spart, spart); GET(g_rinv, rinv);
#undef GET

    cudaFuncSetAttribute(gemm_hmma<1>, cudaFuncAttributeMaxDynamicSharedMemorySize, SMEM_B);
    cudaFuncSetAttribute(gemm_hmma<2>, cudaFuncAttributeMaxDynamicSharedMemorySize, SMEM_B);
    cudaFuncSetAttribute(gemm_hmma<3>, cudaFuncAttributeMaxDynamicSharedMemorySize, SMEM_B);
    cudaFuncSetAttribute(gemm_hmma<4>, cudaFuncAttributeMaxDynamicSharedMemorySize, SMEM_B);

    const int MBN = BATCH * NSEQ;            // 16384

    // 1) splits
    {
        int n4 = BATCH * NSEQ * DDIM / 4;
        split_kernel<<<n4 / 256, 256>>>((const float4*)x, (bf16*)xh, (bf16*)xl, n4);
        split_kernel<<<n4 / 256, 256>>>((const float4*)y, (bf16*)yh, (bf16*)yl, n4);
        int w4 = EDIM * DDIM / 4;
        split_kernel<<<w4 / 256, 256>>>((const float4*)Wq, (bf16*)wqh, (bf16*)wql, w4);
        split_kernel<<<w4 / 256, 256>>>((const float4*)Wk, (bf16*)wkh, (bf16*)wkl, w4);
        split_kernel<<<w4 / 256, 256>>>((const float4*)Wv, (bf16*)wvh, (bf16*)wvl, w4);
        split_kernel<<<w4 / 256, 256>>>((const float4*)Wo, (bf16*)woh, (bf16*)wol, w4);
    }

    // 2) projections: q = y @ Wq^T, k = x @ Wk^T, v = x @ Wv^T (M=16384, N=1024, K=1024)
    {
        dim3 grid(EDIM / 256, MBN / 128, 1);
        gemm_hmma<1><<<grid, 256, SMEM_B>>>((bf16*)yh, (bf16*)yl, (bf16*)wqh, (bf16*)wql,
                                            nullptr, (bf16*)qh, (bf16*)ql, nullptr,
                                            nullptr, nullptr,
                                            MBN, EDIM, DDIM, 0, 0, 0);
        gemm_hmma<1><<<grid, 256, SMEM_B>>>((bf16*)xh, (bf16*)xl, (bf16*)wkh, (bf16*)wkl,
                                            nullptr, (bf16*)kh, (bf16*)kl, nullptr,
                                            nullptr, nullptr,
                                            MBN, EDIM, DDIM, 0, 0, 0);
        gemm_hmma<1><<<grid, 256, SMEM_B>>>((bf16*)xh, (bf16*)xl, (bf16*)wvh, (bf16*)wvl,
                                            nullptr, (bf16*)vh, (bf16*)vl, nullptr,
                                            nullptr, nullptr,
                                            MBN, EDIM, DDIM, 0, 0, 0);
    }

    // 3) scores+exp: E[b] = exp((q[b] @ k[b]^T)/32), split bf16 + row partials
    {
        dim3 grid(NSEQ / 256, NSEQ / 128, BATCH);
        gemm_hmma<3><<<grid, 256, SMEM_B>>>((bf16*)qh, (bf16*)ql, (bf16*)kh, (bf16*)kl,
                                            nullptr, (bf16*)ph, (bf16*)pl, nullptr,
                                            (float*)spart, nullptr,
                                            NSEQ, NSEQ, EDIM,
                                            (long long)NSEQ * EDIM, (long long)NSEQ * EDIM,
                                            (long long)NSEQ * NSEQ);
    }

    // 4) rinv = 1/rowsum
    rowsum_inv<<<MBN / 256, 256>>>((const float*)spart, (float*)rinv, MBN);

    // 4b) transpose V -> V^T per batch
    {
        dim3 grid(EDIM / 64, NSEQ / 64, BATCH);
        transpose_k<<<grid, 256>>>((bf16*)vh, (bf16*)vth);
        transpose_k<<<grid, 256>>>((bf16*)vl, (bf16*)vtl);
    }

    // 5) ctx: C[b] = rinv ⊙ (E[b] @ V[b]) (M=4096, N=1024, K=4096)
    {
        dim3 grid(EDIM / 256, NSEQ / 128, BATCH);
        gemm_hmma<4><<<grid, 256, SMEM_B>>>((bf16*)ph, (bf16*)pl, (bf16*)vth, (bf16*)vtl,
                                            nullptr, (bf16*)ch, (bf16*)cl, nullptr,
                                            nullptr, (const float*)rinv,
                                            NSEQ, EDIM, NSEQ,
                                            (long long)NSEQ * NSEQ, (long long)EDIM * NSEQ,
                                            (long long)NSEQ * EDIM);
    }

    // 6) out = ctx @ Wo^T + bo   (M=16384, N=1024, K=1024)
    {
        dim3 grid(DDIM / 256, MBN / 128, 1);
        gemm_hmma<2><<<grid, 256, SMEM_B>>>((bf16*)ch, (bf16*)cl, (bf16*)woh, (bf16*)wol,
                                            out, nullptr, nullptr, bo,
                                            nullptr, nullptr,
                                            MBN, DDIM, EDIM, 0, 0, 0);
    }

    (void)in_sizes; (void)n_in; (void)out_size;
}